// round 4
// baseline (speedup 1.0000x reference)
#include <cuda_runtime.h>
#include <math.h>

#define B_SZ   2048
#define INV_TEMP (1.0f/0.07f)
#define MARGIN_C 0.15f

#define FMA2(d,a,b,c) asm("fma.rn.f32x2 %0, %1, %2, %3;" : "=l"(d) : "l"(a), "l"(b), "l"(c))
#define UNPACK2(lo,hi,v) asm("mov.b64 {%0, %1}, %2;" : "=f"(lo), "=f"(hi) : "l"(v))

__device__ float        g_partial[B_SZ];
__device__ unsigned int g_count = 0;

typedef unsigned long long ull;

__global__ __launch_bounds__(256, 4)
void loss_kernel(const float* __restrict__ pred,
                 const int*   __restrict__ labels,
                 const float* __restrict__ emb,
                 const float* __restrict__ cpos,
                 const float* __restrict__ conn,
                 float* __restrict__ out)
{
    __shared__ __align__(16) float s_act_emb[4][1024];   // 16 KB
    __shared__ float s_pred[64];
    __shared__ int   s_lab[64];
    __shared__ float s_pos[192];
    __shared__ int   s_act[4];
    __shared__ int   s_inact[60];
    __shared__ float s_topk;
    __shared__ float s_dot[4][64];
    __shared__ float s_norm[64];
    __shared__ float s_rn[64];
    __shared__ float s_bce[64], s_pl[64], s_sp[64], s_nw[64], s_m[64];
    __shared__ int   s_islast;
    __shared__ float s_red[256];

    const int b   = blockIdx.x;
    const int tid = threadIdx.x;
    const int w   = tid >> 5, lane = tid & 31;

    // ---------------- Phase A (no sync): smem scalars + per-warp act list ----------------
    if (tid < 64) { s_pred[tid] = pred[b*64 + tid]; s_lab[tid] = labels[b*64 + tid]; }
    if (tid >= 64 && tid < 256) s_pos[tid - 64] = cpos[tid - 64];

    // every warp: ballot on labels read straight from global (L1/L2 hit)
    const int lab0 = labels[b*64 + lane];
    const int lab1 = labels[b*64 + 32 + lane];
    const unsigned m0 = __ballot_sync(0xffffffffu, lab0 != 0);
    const unsigned m1 = __ballot_sync(0xffffffffu, lab1 != 0);
    int act0, act1, act2, act3;
    {
        int a[4]; int na = 0;
        unsigned mm = m0;
        while (mm) { a[na++] = __ffs(mm) - 1; mm &= mm - 1; }
        mm = m1;
        while (mm) { a[na++] = 32 + __ffs(mm) - 1; mm &= mm - 1; }
        act0 = a[0]; act1 = a[1]; act2 = a[2]; act3 = a[3];
    }

    // warp 0: write act/inact lists to smem (for Phase D)
    if (w == 0) {
        const unsigned below = (1u << lane) - 1u;
        if (lab0) s_act[__popc(m0 & below)] = lane;
        if (lab1) s_act[__popc(m0) + __popc(m1 & below)] = 32 + lane;
        const unsigned i0 = ~m0, i1 = ~m1;
        if (!lab0) s_inact[__popc(i0 & below)] = lane;
        if (!lab1) s_inact[__popc(i0) + __popc(i1 & below)] = 32 + lane;
    }

    // ---------------- Phase B (no sync before): stage 4 active rows ----------------
    {
        const float4* base = (const float4*)(emb + (size_t)b * 65536);
        ((float4*)s_act_emb[0])[tid] = base[(size_t)act0 * 256 + tid];
        ((float4*)s_act_emb[1])[tid] = base[(size_t)act1 * 256 + tid];
        ((float4*)s_act_emb[2])[tid] = base[(size_t)act2 * 256 + tid];
        ((float4*)s_act_emb[3])[tid] = base[(size_t)act3 * 256 + tid];
    }

    // warp 0: parallel top-4 + IoU while Phase B loads are in flight
    if (w == 0) {
        float w0 = pred[b*64 + lane];
        float w1 = pred[b*64 + 32 + lane];
        int inter = 0;
        #pragma unroll
        for (int r = 0; r < 4; ++r) {
            float bv; int bi;
            if (w1 > w0) { bv = w1; bi = lane + 32; } else { bv = w0; bi = lane; }
            #pragma unroll
            for (int off = 16; off; off >>= 1) {
                float ov = __shfl_xor_sync(0xffffffffu, bv, off);
                int   oi = __shfl_xor_sync(0xffffffffu, bi, off);
                if (ov > bv || (ov == bv && oi < bi)) { bv = ov; bi = oi; }
            }
            inter += (bi < 32) ? (int)((m0 >> bi) & 1u) : (int)((m1 >> (bi - 32)) & 1u);
            if (bi == lane)      w0 = -1e30f;
            if (bi == lane + 32) w1 = -1e30f;
        }
        if (lane == 0) {
            float un = (float)(8 - inter);
            s_topk = 1.0f - (float)inter / (un + 1e-8f);
        }
    }
    __syncthreads();

    // ---------------- Phase C: 2 rows/pass, 4 passes, f32x2 FMA ----------------
    {
        const ull zero = 0ull;
        #pragma unroll
        for (int pass = 0; pass < 4; ++pass) {
            const int j0 = w * 8 + pass * 2;
            const ulonglong2* r0 = (const ulonglong2*)(emb + (size_t)b * 65536 + (size_t)j0 * 1024);
            const ulonglong2* r1 = r0 + 256;
            ull d00=zero,d01=zero,d02=zero,d03=zero,n0=zero;
            ull d10=zero,d11=zero,d12=zero,d13=zero,n1=zero;
            #pragma unroll
            for (int ii = 0; ii < 8; ++ii) {
                const int i = lane + ii * 32;
                ulonglong2 e0 = r0[i], e1 = r1[i];
                ulonglong2 a0 = ((const ulonglong2*)s_act_emb[0])[i];
                ulonglong2 a1 = ((const ulonglong2*)s_act_emb[1])[i];
                ulonglong2 a2 = ((const ulonglong2*)s_act_emb[2])[i];
                ulonglong2 a3 = ((const ulonglong2*)s_act_emb[3])[i];
                FMA2(d00,e0.x,a0.x,d00); FMA2(d00,e0.y,a0.y,d00);
                FMA2(d01,e0.x,a1.x,d01); FMA2(d01,e0.y,a1.y,d01);
                FMA2(d02,e0.x,a2.x,d02); FMA2(d02,e0.y,a2.y,d02);
                FMA2(d03,e0.x,a3.x,d03); FMA2(d03,e0.y,a3.y,d03);
                FMA2(n0 ,e0.x,e0.x,n0 ); FMA2(n0 ,e0.y,e0.y,n0 );
                FMA2(d10,e1.x,a0.x,d10); FMA2(d10,e1.y,a0.y,d10);
                FMA2(d11,e1.x,a1.x,d11); FMA2(d11,e1.y,a1.y,d11);
                FMA2(d12,e1.x,a2.x,d12); FMA2(d12,e1.y,a2.y,d12);
                FMA2(d13,e1.x,a3.x,d13); FMA2(d13,e1.y,a3.y,d13);
                FMA2(n1 ,e1.x,e1.x,n1 ); FMA2(n1 ,e1.y,e1.y,n1 );
            }
            float v[10];
            {
                ull acc[10] = {d00,d01,d02,d03,n0, d10,d11,d12,d13,n1};
                #pragma unroll
                for (int t = 0; t < 10; ++t) {
                    float lo, hi; UNPACK2(lo, hi, acc[t]);
                    v[t] = lo + hi;
                }
            }
            #pragma unroll
            for (int off = 16; off; off >>= 1) {
                #pragma unroll
                for (int t = 0; t < 10; ++t)
                    v[t] += __shfl_down_sync(0xffffffffu, v[t], off);
            }
            if (lane == 0) {
                s_dot[0][j0]   = v[0]; s_dot[1][j0]   = v[1];
                s_dot[2][j0]   = v[2]; s_dot[3][j0]   = v[3]; s_norm[j0]   = v[4];
                s_dot[0][j0+1] = v[5]; s_dot[1][j0+1] = v[6];
                s_dot[2][j0+1] = v[7]; s_dot[3][j0+1] = v[8]; s_norm[j0+1] = v[9];
            }
        }
    }
    __syncthreads();

    // ---------------- Phase D ----------------
    if (tid < 64) s_rn[tid] = 1.0f / fmaxf(sqrtf(s_norm[tid]), 1e-12f);

    // per-channel scalar terms (threads 64..127)
    if (tid >= 64 && tid < 128) {
        const int   c   = tid - 64;
        const float p   = s_pred[c];
        const int   lab = s_lab[c];
        s_bce[c] = lab ? logf(p) : log1pf(-p);
        s_pl[c]  = lab ? p : 0.0f;
        const float mi = (p > 0.5f) ? 1.0f : 0.0f;
        s_m[c] = mi;
        float ssum = 0.0f;
        if (mi != 0.0f) {
            const float x = s_pos[c*3], y = s_pos[c*3+1], z = s_pos[c*3+2];
            for (int j = 0; j < 64; ++j) {
                if (j == c) continue;
                if (s_pred[j] > 0.5f) {
                    float dx = x - s_pos[j*3], dy = y - s_pos[j*3+1], dz = z - s_pos[j*3+2];
                    ssum += sqrtf(fmaf(dx,dx, fmaf(dy,dy, dz*dz)));
                }
            }
        }
        s_sp[c] = ssum;
    }

    // network term: each warp handles 8 rows of conn (L2-resident, coalesced)
    {
        const float pl0 = s_pred[lane], pl1 = s_pred[lane + 32];
        #pragma unroll
        for (int rr = 0; rr < 8; ++rr) {
            const int r = w * 8 + rr;
            float t1 = fmaf(conn[r*64 + lane], pl0, conn[r*64 + 32 + lane] * pl1);
            #pragma unroll
            for (int off = 16; off; off >>= 1)
                t1 += __shfl_down_sync(0xffffffffu, t1, off);
            if (lane == 0) s_nw[r] = t1 * s_pred[r];
        }
    }
    __syncthreads();

    // contrastive: 12 pairs in warp 0; negatives for pair p are a contiguous
    // 20-slice of the inactive list (flat reshape aligns on 20|60).
    float ce = 0.0f;
    if (tid < 12) {
        const int p  = tid;
        const int k  = p / 3;
        const int jo = p % 3;
        const int col = jo + (jo >= k ? 1 : 0);
        const int ck = s_act[k];
        const int cj = s_act[col];
        const float rk = s_rn[ck];
        const float l0 = s_dot[k][cj] * rk * s_rn[cj] * INV_TEMP;
        const int base = 20 * jo;
        float mx = l0;
        #pragma unroll
        for (int n = 0; n < 20; ++n) {
            int c = s_inact[base + n];
            float vv = s_dot[k][c] * rk * s_rn[c] * INV_TEMP;
            mx = fmaxf(mx, vv);
        }
        float ssum = expf(l0 - mx);
        #pragma unroll
        for (int n = 0; n < 20; ++n) {
            int c = s_inact[base + n];
            float vv = s_dot[k][c] * rk * s_rn[c] * INV_TEMP;
            ssum += expf(vv - mx);
        }
        ce = logf(ssum) + mx - l0;
    }
    if (tid < 32) {
        #pragma unroll
        for (int off = 16; off; off >>= 1) ce += __shfl_down_sync(0xffffffffu, ce, off);
    }

    if (tid < 32) {
        float r_bce = s_bce[tid] + s_bce[tid+32];
        float r_pl  = s_pl [tid] + s_pl [tid+32];
        float r_p   = s_pred[tid] + s_pred[tid+32];
        float r_lab = (float)s_lab[tid] + (float)s_lab[tid+32];
        float r_sp  = s_sp[tid] + s_sp[tid+32];
        float r_nw  = s_nw[tid] + s_nw[tid+32];
        float r_m   = s_m [tid] + s_m [tid+32];
        #pragma unroll
        for (int off = 16; off; off >>= 1) {
            r_bce += __shfl_down_sync(0xffffffffu, r_bce, off);
            r_pl  += __shfl_down_sync(0xffffffffu, r_pl , off);
            r_p   += __shfl_down_sync(0xffffffffu, r_p  , off);
            r_lab += __shfl_down_sync(0xffffffffu, r_lab, off);
            r_sp  += __shfl_down_sync(0xffffffffu, r_sp , off);
            r_nw  += __shfl_down_sync(0xffffffffu, r_nw , off);
            r_m   += __shfl_down_sync(0xffffffffu, r_m  , off);
        }
        if (tid == 0) {
            float score_b    = -r_bce * (1.0f/64.0f);
            float act_mean   = r_pl / r_lab;
            float inact_mean = (r_p - r_pl) / (64.0f - r_lab);
            float margin_b   = fmaxf(MARGIN_C - (act_mean - inact_mean), 0.0f);
            float contr_b    = ce * (1.0f/12.0f);
            float nm         = r_m;
            float spatial_b  = (nm >= 2.0f) ? r_sp / fmaxf(nm*(nm-1.0f), 1.0f) : 0.0f;
            float net_b      = -r_nw * (1.0f/4096.0f);
            g_partial[b] = 3.0f*score_b + 1.0f*margin_b + 2.0f*s_topk
                         + 1.0f*contr_b + 0.5f*spatial_b + 0.5f*net_b;
        }
    }

    // ---------------- fused final reduction (last block) ----------------
    if (tid == 0) {
        __threadfence();
        unsigned int v = atomicAdd(&g_count, 1u);
        s_islast = (v == (unsigned)(B_SZ - 1));
    }
    __syncthreads();
    if (s_islast) {
        float s = 0.0f;
        for (int i = tid; i < B_SZ; i += blockDim.x) s += g_partial[i];
        s_red[tid] = s;
        __syncthreads();
        for (int o = 128; o > 0; o >>= 1) {
            if (tid < o) s_red[tid] += s_red[tid + o];
            __syncthreads();
        }
        if (tid == 0) { out[0] = s_red[0] * (1.0f / (float)B_SZ); g_count = 0; }
    }
}

extern "C" void kernel_launch(void* const* d_in, const int* in_sizes, int n_in,
                              void* d_out, int out_size)
{
    const float* pred = (const float*)d_in[0];
    const int*   lab  = (const int*)  d_in[1];
    const float* emb  = (const float*)d_in[2];
    const float* cpos = (const float*)d_in[3];
    const float* conn = (const float*)d_in[4];
    loss_kernel<<<B_SZ, 256>>>(pred, lab, emb, cpos, conn, (float*)d_out);
}

// round 5
// speedup vs baseline: 1.1566x; 1.1566x over previous
#include <cuda_runtime.h>
#include <math.h>

#define B_SZ   2048
#define INV_TEMP (1.0f/0.07f)
#define MARGIN_C 0.15f

#define FMA2(d,a,b,c) asm("fma.rn.f32x2 %0, %1, %2, %3;" : "=l"(d) : "l"(a), "l"(b), "l"(c))
#define UNPACK2(lo,hi,v) asm("mov.b64 {%0, %1}, %2;" : "=f"(lo), "=f"(hi) : "l"(v))

__device__ float        g_partial[B_SZ];
__device__ unsigned int g_count = 0;

typedef unsigned long long ull;

__global__ __launch_bounds__(256, 3)
void loss_kernel(const float* __restrict__ pred,
                 const int*   __restrict__ labels,
                 const float* __restrict__ emb,
                 const float* __restrict__ cpos,
                 const float* __restrict__ conn,
                 float* __restrict__ out)
{
    __shared__ __align__(16) float s_act_emb[4][1024];   // 16 KB
    __shared__ float s_pred[64];
    __shared__ int   s_lab[64];
    __shared__ float s_pos[192];
    __shared__ int   s_act[4];
    __shared__ int   s_inact[60];
    __shared__ float s_topk;
    __shared__ float s_dot[4][64];
    __shared__ float s_norm[64];
    __shared__ float s_rn[64];
    __shared__ float s_bce[64], s_pl[64], s_sp[64], s_nw[64], s_m[64];
    __shared__ int   s_islast;
    __shared__ float s_red[256];

    const int b   = blockIdx.x;
    const int tid = threadIdx.x;
    const int w   = tid >> 5, lane = tid & 31;

    // ---------------- Phase A (no sync): smem scalars + per-warp act list ----------------
    if (tid < 64) { s_pred[tid] = pred[b*64 + tid]; s_lab[tid] = labels[b*64 + tid]; }
    if (tid >= 64 && tid < 256) s_pos[tid - 64] = cpos[tid - 64];

    // every warp: ballot on labels read straight from global (L1/L2 hit)
    const int lab0 = labels[b*64 + lane];
    const int lab1 = labels[b*64 + 32 + lane];
    const unsigned m0 = __ballot_sync(0xffffffffu, lab0 != 0);
    const unsigned m1 = __ballot_sync(0xffffffffu, lab1 != 0);
    int act0, act1, act2, act3;
    {
        int a[4]; int na = 0;
        unsigned mm = m0;
        while (mm) { a[na++] = __ffs(mm) - 1; mm &= mm - 1; }
        mm = m1;
        while (mm) { a[na++] = 32 + __ffs(mm) - 1; mm &= mm - 1; }
        act0 = a[0]; act1 = a[1]; act2 = a[2]; act3 = a[3];
    }

    // warp 0: write act/inact lists to smem (for Phase D)
    if (w == 0) {
        const unsigned below = (1u << lane) - 1u;
        if (lab0) s_act[__popc(m0 & below)] = lane;
        if (lab1) s_act[__popc(m0) + __popc(m1 & below)] = 32 + lane;
        const unsigned i0 = ~m0, i1 = ~m1;
        if (!lab0) s_inact[__popc(i0 & below)] = lane;
        if (!lab1) s_inact[__popc(i0) + __popc(i1 & below)] = 32 + lane;
    }

    // ---------------- Phase B (no sync before): stage 4 active rows ----------------
    {
        const float4* base = (const float4*)(emb + (size_t)b * 65536);
        ((float4*)s_act_emb[0])[tid] = base[(size_t)act0 * 256 + tid];
        ((float4*)s_act_emb[1])[tid] = base[(size_t)act1 * 256 + tid];
        ((float4*)s_act_emb[2])[tid] = base[(size_t)act2 * 256 + tid];
        ((float4*)s_act_emb[3])[tid] = base[(size_t)act3 * 256 + tid];
    }

    // warp 0: parallel top-4 + IoU while Phase B loads are in flight
    if (w == 0) {
        float w0 = pred[b*64 + lane];
        float w1 = pred[b*64 + 32 + lane];
        int inter = 0;
        #pragma unroll
        for (int r = 0; r < 4; ++r) {
            float bv; int bi;
            if (w1 > w0) { bv = w1; bi = lane + 32; } else { bv = w0; bi = lane; }
            #pragma unroll
            for (int off = 16; off; off >>= 1) {
                float ov = __shfl_xor_sync(0xffffffffu, bv, off);
                int   oi = __shfl_xor_sync(0xffffffffu, bi, off);
                if (ov > bv || (ov == bv && oi < bi)) { bv = ov; bi = oi; }
            }
            inter += (bi < 32) ? (int)((m0 >> bi) & 1u) : (int)((m1 >> (bi - 32)) & 1u);
            if (bi == lane)      w0 = -1e30f;
            if (bi == lane + 32) w1 = -1e30f;
        }
        if (lane == 0) {
            float un = (float)(8 - inter);
            s_topk = 1.0f - (float)inter / (un + 1e-8f);
        }
    }
    __syncthreads();

    // ---------------- Phase C: 2 rows/pass, 4 passes, f32x2 FMA (no local arrays) ----------------
    {
        const ull zero = 0ull;
        #pragma unroll
        for (int pass = 0; pass < 4; ++pass) {
            const int j0 = w * 8 + pass * 2;
            const ulonglong2* r0 = (const ulonglong2*)(emb + (size_t)b * 65536 + (size_t)j0 * 1024);
            const ulonglong2* r1 = r0 + 256;
            ull d00=zero,d01=zero,d02=zero,d03=zero,n0=zero;
            ull d10=zero,d11=zero,d12=zero,d13=zero,n1=zero;
            #pragma unroll
            for (int ii = 0; ii < 8; ++ii) {
                const int i = lane + ii * 32;
                ulonglong2 e0 = r0[i], e1 = r1[i];
                ulonglong2 a0 = ((const ulonglong2*)s_act_emb[0])[i];
                FMA2(d00,e0.x,a0.x,d00); FMA2(d00,e0.y,a0.y,d00);
                FMA2(d10,e1.x,a0.x,d10); FMA2(d10,e1.y,a0.y,d10);
                ulonglong2 a1 = ((const ulonglong2*)s_act_emb[1])[i];
                FMA2(d01,e0.x,a1.x,d01); FMA2(d01,e0.y,a1.y,d01);
                FMA2(d11,e1.x,a1.x,d11); FMA2(d11,e1.y,a1.y,d11);
                ulonglong2 a2 = ((const ulonglong2*)s_act_emb[2])[i];
                FMA2(d02,e0.x,a2.x,d02); FMA2(d02,e0.y,a2.y,d02);
                FMA2(d12,e1.x,a2.x,d12); FMA2(d12,e1.y,a2.y,d12);
                ulonglong2 a3 = ((const ulonglong2*)s_act_emb[3])[i];
                FMA2(d03,e0.x,a3.x,d03); FMA2(d03,e0.y,a3.y,d03);
                FMA2(d13,e1.x,a3.x,d13); FMA2(d13,e1.y,a3.y,d13);
                FMA2(n0 ,e0.x,e0.x,n0 ); FMA2(n0 ,e0.y,e0.y,n0 );
                FMA2(n1 ,e1.x,e1.x,n1 ); FMA2(n1 ,e1.y,e1.y,n1 );
            }
            float v0,v1,v2,v3,v4,v5,v6,v7,v8,v9;
            { float lo,hi; UNPACK2(lo,hi,d00); v0=lo+hi; }
            { float lo,hi; UNPACK2(lo,hi,d01); v1=lo+hi; }
            { float lo,hi; UNPACK2(lo,hi,d02); v2=lo+hi; }
            { float lo,hi; UNPACK2(lo,hi,d03); v3=lo+hi; }
            { float lo,hi; UNPACK2(lo,hi,n0 ); v4=lo+hi; }
            { float lo,hi; UNPACK2(lo,hi,d10); v5=lo+hi; }
            { float lo,hi; UNPACK2(lo,hi,d11); v6=lo+hi; }
            { float lo,hi; UNPACK2(lo,hi,d12); v7=lo+hi; }
            { float lo,hi; UNPACK2(lo,hi,d13); v8=lo+hi; }
            { float lo,hi; UNPACK2(lo,hi,n1 ); v9=lo+hi; }
            #pragma unroll
            for (int off = 16; off; off >>= 1) {
                v0 += __shfl_down_sync(0xffffffffu, v0, off);
                v1 += __shfl_down_sync(0xffffffffu, v1, off);
                v2 += __shfl_down_sync(0xffffffffu, v2, off);
                v3 += __shfl_down_sync(0xffffffffu, v3, off);
                v4 += __shfl_down_sync(0xffffffffu, v4, off);
                v5 += __shfl_down_sync(0xffffffffu, v5, off);
                v6 += __shfl_down_sync(0xffffffffu, v6, off);
                v7 += __shfl_down_sync(0xffffffffu, v7, off);
                v8 += __shfl_down_sync(0xffffffffu, v8, off);
                v9 += __shfl_down_sync(0xffffffffu, v9, off);
            }
            if (lane == 0) {
                s_dot[0][j0]   = v0; s_dot[1][j0]   = v1;
                s_dot[2][j0]   = v2; s_dot[3][j0]   = v3; s_norm[j0]   = v4;
                s_dot[0][j0+1] = v5; s_dot[1][j0+1] = v6;
                s_dot[2][j0+1] = v7; s_dot[3][j0+1] = v8; s_norm[j0+1] = v9;
            }
        }
    }
    __syncthreads();

    // ---------------- Phase D ----------------
    if (tid < 64) s_rn[tid] = 1.0f / fmaxf(sqrtf(s_norm[tid]), 1e-12f);

    // per-channel scalar terms (threads 64..127)
    if (tid >= 64 && tid < 128) {
        const int   c   = tid - 64;
        const float p   = s_pred[c];
        const int   lab = s_lab[c];
        s_bce[c] = lab ? logf(p) : log1pf(-p);
        s_pl[c]  = lab ? p : 0.0f;
        const float mi = (p > 0.5f) ? 1.0f : 0.0f;
        s_m[c] = mi;
        float ssum = 0.0f;
        if (mi != 0.0f) {
            const float x = s_pos[c*3], y = s_pos[c*3+1], z = s_pos[c*3+2];
            for (int j = 0; j < 64; ++j) {
                if (j == c) continue;
                if (s_pred[j] > 0.5f) {
                    float dx = x - s_pos[j*3], dy = y - s_pos[j*3+1], dz = z - s_pos[j*3+2];
                    ssum += sqrtf(fmaf(dx,dx, fmaf(dy,dy, dz*dz)));
                }
            }
        }
        s_sp[c] = ssum;
    }

    // network term: each warp handles 8 rows of conn (L2-resident, coalesced)
    {
        const float pl0 = s_pred[lane], pl1 = s_pred[lane + 32];
        #pragma unroll
        for (int rr = 0; rr < 8; ++rr) {
            const int r = w * 8 + rr;
            float t1 = fmaf(conn[r*64 + lane], pl0, conn[r*64 + 32 + lane] * pl1);
            #pragma unroll
            for (int off = 16; off; off >>= 1)
                t1 += __shfl_down_sync(0xffffffffu, t1, off);
            if (lane == 0) s_nw[r] = t1 * s_pred[r];
        }
    }
    __syncthreads();

    // contrastive: 12 pairs in warp 0; negatives for pair p are a contiguous
    // 20-slice of the inactive list (flat reshape aligns on 20|60).
    float ce = 0.0f;
    if (tid < 12) {
        const int p  = tid;
        const int k  = p / 3;
        const int jo = p % 3;
        const int col = jo + (jo >= k ? 1 : 0);
        const int ck = s_act[k];
        const int cj = s_act[col];
        const float rk = s_rn[ck];
        const float l0 = s_dot[k][cj] * rk * s_rn[cj] * INV_TEMP;
        const int base = 20 * jo;
        float mx = l0;
        #pragma unroll
        for (int n = 0; n < 20; ++n) {
            int c = s_inact[base + n];
            float vv = s_dot[k][c] * rk * s_rn[c] * INV_TEMP;
            mx = fmaxf(mx, vv);
        }
        float ssum = expf(l0 - mx);
        #pragma unroll
        for (int n = 0; n < 20; ++n) {
            int c = s_inact[base + n];
            float vv = s_dot[k][c] * rk * s_rn[c] * INV_TEMP;
            ssum += expf(vv - mx);
        }
        ce = logf(ssum) + mx - l0;
    }
    if (tid < 32) {
        #pragma unroll
        for (int off = 16; off; off >>= 1) ce += __shfl_down_sync(0xffffffffu, ce, off);
    }

    if (tid < 32) {
        float r_bce = s_bce[tid] + s_bce[tid+32];
        float r_pl  = s_pl [tid] + s_pl [tid+32];
        float r_p   = s_pred[tid] + s_pred[tid+32];
        float r_lab = (float)s_lab[tid] + (float)s_lab[tid+32];
        float r_sp  = s_sp[tid] + s_sp[tid+32];
        float r_nw  = s_nw[tid] + s_nw[tid+32];
        float r_m   = s_m [tid] + s_m [tid+32];
        #pragma unroll
        for (int off = 16; off; off >>= 1) {
            r_bce += __shfl_down_sync(0xffffffffu, r_bce, off);
            r_pl  += __shfl_down_sync(0xffffffffu, r_pl , off);
            r_p   += __shfl_down_sync(0xffffffffu, r_p  , off);
            r_lab += __shfl_down_sync(0xffffffffu, r_lab, off);
            r_sp  += __shfl_down_sync(0xffffffffu, r_sp , off);
            r_nw  += __shfl_down_sync(0xffffffffu, r_nw , off);
            r_m   += __shfl_down_sync(0xffffffffu, r_m  , off);
        }
        if (tid == 0) {
            float score_b    = -r_bce * (1.0f/64.0f);
            float act_mean   = r_pl / r_lab;
            float inact_mean = (r_p - r_pl) / (64.0f - r_lab);
            float margin_b   = fmaxf(MARGIN_C - (act_mean - inact_mean), 0.0f);
            float contr_b    = ce * (1.0f/12.0f);
            float nm         = r_m;
            float spatial_b  = (nm >= 2.0f) ? r_sp / fmaxf(nm*(nm-1.0f), 1.0f) : 0.0f;
            float net_b      = -r_nw * (1.0f/4096.0f);
            g_partial[b] = 3.0f*score_b + 1.0f*margin_b + 2.0f*s_topk
                         + 1.0f*contr_b + 0.5f*spatial_b + 0.5f*net_b;
        }
    }

    // ---------------- fused final reduction (last block) ----------------
    if (tid == 0) {
        __threadfence();
        unsigned int v = atomicAdd(&g_count, 1u);
        s_islast = (v == (unsigned)(B_SZ - 1));
    }
    __syncthreads();
    if (s_islast) {
        float s = 0.0f;
        for (int i = tid; i < B_SZ; i += blockDim.x) s += g_partial[i];
        s_red[tid] = s;
        __syncthreads();
        for (int o = 128; o > 0; o >>= 1) {
            if (tid < o) s_red[tid] += s_red[tid + o];
            __syncthreads();
        }
        if (tid == 0) { out[0] = s_red[0] * (1.0f / (float)B_SZ); g_count = 0; }
    }
}

extern "C" void kernel_launch(void* const* d_in, const int* in_sizes, int n_in,
                              void* d_out, int out_size)
{
    const float* pred = (const float*)d_in[0];
    const int*   lab  = (const int*)  d_in[1];
    const float* emb  = (const float*)d_in[2];
    const float* cpos = (const float*)d_in[3];
    const float* conn = (const float*)d_in[4];
    loss_kernel<<<B_SZ, 256>>>(pred, lab, emb, cpos, conn, (float*)d_out);
}

// round 7
// speedup vs baseline: 1.3504x; 1.1675x over previous
#include <cuda_runtime.h>
#include <math.h>

#define B_SZ   2048
#define INV_TEMP (1.0f/0.07f)
#define MARGIN_C 0.15f

#define FMA2(d,a,b,c) asm("fma.rn.f32x2 %0, %1, %2, %3;" : "=l"(d) : "l"(a), "l"(b), "l"(c))
#define UNPACK2(lo,hi,v) asm("mov.b64 {%0, %1}, %2;" : "=f"(lo), "=f"(hi) : "l"(v))

__device__ float        g_partial[B_SZ];
__device__ unsigned int g_count = 0;

typedef unsigned long long ull;

__global__ __launch_bounds__(256, 2)
void loss_kernel(const float* __restrict__ pred,
                 const int*   __restrict__ labels,
                 const float* __restrict__ emb,
                 const float* __restrict__ cpos,
                 const float* __restrict__ conn,
                 float* __restrict__ out)
{
    __shared__ __align__(16) float s_act_emb[4][1024];   // 16 KB
    __shared__ float s_pred[64];
    __shared__ int   s_lab[64];
    __shared__ float s_pos[192];
    __shared__ int   s_act[4];
    __shared__ int   s_inact[60];
    __shared__ float s_topk;
    __shared__ float s_dot[4][64];
    __shared__ float s_norm[64];
    __shared__ float s_rn[64];
    __shared__ float s_bce[64], s_pl[64], s_sp[64], s_nw[64], s_m[64];
    __shared__ int   s_islast;
    __shared__ float s_red[256];

    const int b   = blockIdx.x;
    const int tid = threadIdx.x;
    const int w   = tid >> 5, lane = tid & 31;

    // ---------------- Phase A (no sync): smem scalars + per-warp act list ----------------
    if (tid < 64) { s_pred[tid] = pred[b*64 + tid]; s_lab[tid] = labels[b*64 + tid]; }
    if (tid >= 64 && tid < 256) s_pos[tid - 64] = cpos[tid - 64];

    const int lab0 = labels[b*64 + lane];
    const int lab1 = labels[b*64 + 32 + lane];
    const unsigned m0 = __ballot_sync(0xffffffffu, lab0 != 0);
    const unsigned m1 = __ballot_sync(0xffffffffu, lab1 != 0);
    int act0, act1, act2, act3;
    {
        int a[4]; int na = 0;
        unsigned mm = m0;
        while (mm) { a[na++] = __ffs(mm) - 1; mm &= mm - 1; }
        mm = m1;
        while (mm) { a[na++] = 32 + __ffs(mm) - 1; mm &= mm - 1; }
        act0 = a[0]; act1 = a[1]; act2 = a[2]; act3 = a[3];
    }

    if (w == 0) {
        const unsigned below = (1u << lane) - 1u;
        if (lab0) s_act[__popc(m0 & below)] = lane;
        if (lab1) s_act[__popc(m0) + __popc(m1 & below)] = 32 + lane;
        const unsigned i0 = ~m0, i1 = ~m1;
        if (!lab0) s_inact[__popc(i0 & below)] = lane;
        if (!lab1) s_inact[__popc(i0) + __popc(i1 & below)] = 32 + lane;
    }

    // ---------------- Phase B (no sync before): stage 4 active rows ----------------
    {
        const float4* base = (const float4*)(emb + (size_t)b * 65536);
        ((float4*)s_act_emb[0])[tid] = base[(size_t)act0 * 256 + tid];
        ((float4*)s_act_emb[1])[tid] = base[(size_t)act1 * 256 + tid];
        ((float4*)s_act_emb[2])[tid] = base[(size_t)act2 * 256 + tid];
        ((float4*)s_act_emb[3])[tid] = base[(size_t)act3 * 256 + tid];
    }

    // warp 0: parallel top-4 + IoU while Phase B loads are in flight
    if (w == 0) {
        float w0 = pred[b*64 + lane];
        float w1 = pred[b*64 + 32 + lane];
        int inter = 0;
        #pragma unroll
        for (int r = 0; r < 4; ++r) {
            float bv; int bi;
            if (w1 > w0) { bv = w1; bi = lane + 32; } else { bv = w0; bi = lane; }
            #pragma unroll
            for (int off = 16; off; off >>= 1) {
                float ov = __shfl_xor_sync(0xffffffffu, bv, off);
                int   oi = __shfl_xor_sync(0xffffffffu, bi, off);
                if (ov > bv || (ov == bv && oi < bi)) { bv = ov; bi = oi; }
            }
            inter += (bi < 32) ? (int)((m0 >> bi) & 1u) : (int)((m1 >> (bi - 32)) & 1u);
            if (bi == lane)      w0 = -1e30f;
            if (bi == lane + 32) w1 = -1e30f;
        }
        if (lane == 0) {
            float un = (float)(8 - inter);
            s_topk = 1.0f - (float)inter / (un + 1e-8f);
        }
    }
    __syncthreads();

    // ---------------- Phase C: 2 rows/pass, depth-3 software-pipelined loads ----------------
    {
        const ull zero = 0ull;
        #pragma unroll
        for (int pass = 0; pass < 4; ++pass) {
            const int j0 = w * 8 + pass * 2;
            const ulonglong2* r0 = (const ulonglong2*)(emb + (size_t)b * 65536 + (size_t)j0 * 1024);
            const ulonglong2* r1 = r0 + 256;
            ull d00=zero,d01=zero,d02=zero,d03=zero,n0=zero;
            ull d10=zero,d11=zero,d12=zero,d13=zero,n1=zero;

            // prologue: 3 iterations of stream loads in flight
            ulonglong2 e0p0 = r0[lane];       ulonglong2 e1p0 = r1[lane];
            ulonglong2 e0p1 = r0[lane + 32];  ulonglong2 e1p1 = r1[lane + 32];
            ulonglong2 e0p2 = r0[lane + 64];  ulonglong2 e1p2 = r1[lane + 64];

            #pragma unroll
            for (int ii = 0; ii < 8; ++ii) {
                const ulonglong2 e0 = e0p0, e1 = e1p0;
                // rotate pipeline registers (free in fully unrolled code)
                e0p0 = e0p1; e1p0 = e1p1;
                e0p1 = e0p2; e1p1 = e1p2;
                if (ii < 5) {                 // refill depth-3 slot
                    e0p2 = r0[lane + (ii + 3) * 32];
                    e1p2 = r1[lane + (ii + 3) * 32];
                }
                const int i = lane + ii * 32;
                ulonglong2 a0 = ((const ulonglong2*)s_act_emb[0])[i];
                FMA2(d00,e0.x,a0.x,d00); FMA2(d00,e0.y,a0.y,d00);
                FMA2(d10,e1.x,a0.x,d10); FMA2(d10,e1.y,a0.y,d10);
                ulonglong2 a1 = ((const ulonglong2*)s_act_emb[1])[i];
                FMA2(d01,e0.x,a1.x,d01); FMA2(d01,e0.y,a1.y,d01);
                FMA2(d11,e1.x,a1.x,d11); FMA2(d11,e1.y,a1.y,d11);
                ulonglong2 a2 = ((const ulonglong2*)s_act_emb[2])[i];
                FMA2(d02,e0.x,a2.x,d02); FMA2(d02,e0.y,a2.y,d02);
                FMA2(d12,e1.x,a2.x,d12); FMA2(d12,e1.y,a2.y,d12);
                ulonglong2 a3 = ((const ulonglong2*)s_act_emb[3])[i];
                FMA2(d03,e0.x,a3.x,d03); FMA2(d03,e0.y,a3.y,d03);
                FMA2(d13,e1.x,a3.x,d13); FMA2(d13,e1.y,a3.y,d13);
                FMA2(n0 ,e0.x,e0.x,n0 ); FMA2(n0 ,e0.y,e0.y,n0 );
                FMA2(n1 ,e1.x,e1.x,n1 ); FMA2(n1 ,e1.y,e1.y,n1 );
            }
            float v0,v1,v2,v3,v4,v5,v6,v7,v8,v9;
            { float lo,hi; UNPACK2(lo,hi,d00); v0=lo+hi; }
            { float lo,hi; UNPACK2(lo,hi,d01); v1=lo+hi; }
            { float lo,hi; UNPACK2(lo,hi,d02); v2=lo+hi; }
            { float lo,hi; UNPACK2(lo,hi,d03); v3=lo+hi; }
            { float lo,hi; UNPACK2(lo,hi,n0 ); v4=lo+hi; }
            { float lo,hi; UNPACK2(lo,hi,d10); v5=lo+hi; }
            { float lo,hi; UNPACK2(lo,hi,d11); v6=lo+hi; }
            { float lo,hi; UNPACK2(lo,hi,d12); v7=lo+hi; }
            { float lo,hi; UNPACK2(lo,hi,d13); v8=lo+hi; }
            { float lo,hi; UNPACK2(lo,hi,n1 ); v9=lo+hi; }
            #pragma unroll
            for (int off = 16; off; off >>= 1) {
                v0 += __shfl_down_sync(0xffffffffu, v0, off);
                v1 += __shfl_down_sync(0xffffffffu, v1, off);
                v2 += __shfl_down_sync(0xffffffffu, v2, off);
                v3 += __shfl_down_sync(0xffffffffu, v3, off);
                v4 += __shfl_down_sync(0xffffffffu, v4, off);
                v5 += __shfl_down_sync(0xffffffffu, v5, off);
                v6 += __shfl_down_sync(0xffffffffu, v6, off);
                v7 += __shfl_down_sync(0xffffffffu, v7, off);
                v8 += __shfl_down_sync(0xffffffffu, v8, off);
                v9 += __shfl_down_sync(0xffffffffu, v9, off);
            }
            if (lane == 0) {
                s_dot[0][j0]   = v0; s_dot[1][j0]   = v1;
                s_dot[2][j0]   = v2; s_dot[3][j0]   = v3; s_norm[j0]   = v4;
                s_dot[0][j0+1] = v5; s_dot[1][j0+1] = v6;
                s_dot[2][j0+1] = v7; s_dot[3][j0+1] = v8; s_norm[j0+1] = v9;
            }
        }
    }
    __syncthreads();

    // ---------------- Phase D ----------------
    if (tid < 64) s_rn[tid] = 1.0f / fmaxf(sqrtf(s_norm[tid]), 1e-12f);

    if (tid >= 64 && tid < 128) {
        const int   c   = tid - 64;
        const float p   = s_pred[c];
        const int   lab = s_lab[c];
        s_bce[c] = lab ? logf(p) : log1pf(-p);
        s_pl[c]  = lab ? p : 0.0f;
        const float mi = (p > 0.5f) ? 1.0f : 0.0f;
        s_m[c] = mi;
        float ssum = 0.0f;
        if (mi != 0.0f) {
            const float x = s_pos[c*3], y = s_pos[c*3+1], z = s_pos[c*3+2];
            for (int j = 0; j < 64; ++j) {
                if (j == c) continue;
                if (s_pred[j] > 0.5f) {
                    float dx = x - s_pos[j*3], dy = y - s_pos[j*3+1], dz = z - s_pos[j*3+2];
                    ssum += sqrtf(fmaf(dx,dx, fmaf(dy,dy, dz*dz)));
                }
            }
        }
        s_sp[c] = ssum;
    }

    // network term: each warp handles 8 rows of conn (L2-resident, coalesced)
    {
        const float pl0 = s_pred[lane], pl1 = s_pred[lane + 32];
        #pragma unroll
        for (int rr = 0; rr < 8; ++rr) {
            const int r = w * 8 + rr;
            float t1 = fmaf(conn[r*64 + lane], pl0, conn[r*64 + 32 + lane] * pl1);
            #pragma unroll
            for (int off = 16; off; off >>= 1)
                t1 += __shfl_down_sync(0xffffffffu, t1, off);
            if (lane == 0) s_nw[r] = t1 * s_pred[r];
        }
    }
    __syncthreads();

    // contrastive: 12 pairs in warp 0
    float ce = 0.0f;
    if (tid < 12) {
        const int p  = tid;
        const int k  = p / 3;
        const int jo = p % 3;
        const int col = jo + (jo >= k ? 1 : 0);
        const int ck = s_act[k];
        const int cj = s_act[col];
        const float rk = s_rn[ck];
        const float l0 = s_dot[k][cj] * rk * s_rn[cj] * INV_TEMP;
        const int base = 20 * jo;
        float mx = l0;
        #pragma unroll
        for (int n = 0; n < 20; ++n) {
            int c = s_inact[base + n];
            float vv = s_dot[k][c] * rk * s_rn[c] * INV_TEMP;
            mx = fmaxf(mx, vv);
        }
        float ssum = expf(l0 - mx);
        #pragma unroll
        for (int n = 0; n < 20; ++n) {
            int c = s_inact[base + n];
            float vv = s_dot[k][c] * rk * s_rn[c] * INV_TEMP;
            ssum += expf(vv - mx);
        }
        ce = logf(ssum) + mx - l0;
    }
    if (tid < 32) {
        #pragma unroll
        for (int off = 16; off; off >>= 1) ce += __shfl_down_sync(0xffffffffu, ce, off);
    }

    if (tid < 32) {
        float r_bce = s_bce[tid] + s_bce[tid+32];
        float r_pl  = s_pl [tid] + s_pl [tid+32];
        float r_p   = s_pred[tid] + s_pred[tid+32];
        float r_lab = (float)s_lab[tid] + (float)s_lab[tid+32];
        float r_sp  = s_sp[tid] + s_sp[tid+32];
        float r_nw  = s_nw[tid] + s_nw[tid+32];
        float r_m   = s_m [tid] + s_m [tid+32];
        #pragma unroll
        for (int off = 16; off; off >>= 1) {
            r_bce += __shfl_down_sync(0xffffffffu, r_bce, off);
            r_pl  += __shfl_down_sync(0xffffffffu, r_pl , off);
            r_p   += __shfl_down_sync(0xffffffffu, r_p  , off);
            r_lab += __shfl_down_sync(0xffffffffu, r_lab, off);
            r_sp  += __shfl_down_sync(0xffffffffu, r_sp , off);
            r_nw  += __shfl_down_sync(0xffffffffu, r_nw , off);
            r_m   += __shfl_down_sync(0xffffffffu, r_m  , off);
        }
        if (tid == 0) {
            float score_b    = -r_bce * (1.0f/64.0f);
            float act_mean   = r_pl / r_lab;
            float inact_mean = (r_p - r_pl) / (64.0f - r_lab);
            float margin_b   = fmaxf(MARGIN_C - (act_mean - inact_mean), 0.0f);
            float contr_b    = ce * (1.0f/12.0f);
            float nm         = r_m;
            float spatial_b  = (nm >= 2.0f) ? r_sp / fmaxf(nm*(nm-1.0f), 1.0f) : 0.0f;
            float net_b      = -r_nw * (1.0f/4096.0f);
            g_partial[b] = 3.0f*score_b + 1.0f*margin_b + 2.0f*s_topk
                         + 1.0f*contr_b + 0.5f*spatial_b + 0.5f*net_b;
        }
    }

    // ---------------- fused final reduction (last block) ----------------
    if (tid == 0) {
        __threadfence();
        unsigned int v = atomicAdd(&g_count, 1u);
        s_islast = (v == (unsigned)(B_SZ - 1));
    }
    __syncthreads();
    if (s_islast) {
        float s = 0.0f;
        for (int i = tid; i < B_SZ; i += blockDim.x) s += g_partial[i];
        s_red[tid] = s;
        __syncthreads();
        for (int o = 128; o > 0; o >>= 1) {
            if (tid < o) s_red[tid] += s_red[tid + o];
            __syncthreads();
        }
        if (tid == 0) { out[0] = s_red[0] * (1.0f / (float)B_SZ); g_count = 0; }
    }
}

extern "C" void kernel_launch(void* const* d_in, const int* in_sizes, int n_in,
                              void* d_out, int out_size)
{
    const float* pred = (const float*)d_in[0];
    const int*   lab  = (const int*)  d_in[1];
    const float* emb  = (const float*)d_in[2];
    const float* cpos = (const float*)d_in[3];
    const float* conn = (const float*)d_in[4];
    loss_kernel<<<B_SZ, 256>>>(pred, lab, emb, cpos, conn, (float*)d_out);
}

// round 8
// speedup vs baseline: 1.4600x; 1.0812x over previous
#include <cuda_runtime.h>
#include <math.h>

#define B_SZ   2048
#define INV_TEMP (1.0f/0.07f)
#define MARGIN_C 0.15f

#define FMA2(d,a,b,c) asm("fma.rn.f32x2 %0, %1, %2, %3;" : "=l"(d) : "l"(a), "l"(b), "l"(c))
#define UNPACK2(lo,hi,v) asm("mov.b64 {%0, %1}, %2;" : "=f"(lo), "=f"(hi) : "l"(v))

__device__ float        g_partial[B_SZ];
__device__ unsigned int g_count = 0;
__device__ float        g_dist[64][64];

typedef unsigned long long ull;

// ---- tiny precompute: dist[i][j] = sqrt(|pos_i - pos_j|^2 + eye) * (1-eye) ----
__global__ void dist_kernel(const float* __restrict__ cpos)
{
    __shared__ float s_pos[192];
    const int tid = threadIdx.x;          // 256 threads
    if (tid < 192) s_pos[tid] = cpos[tid];
    __syncthreads();
    #pragma unroll
    for (int e = 0; e < 16; ++e) {
        const int idx = tid * 16 + e;
        const int i = idx >> 6, j = idx & 63;
        float dx = s_pos[i*3]   - s_pos[j*3];
        float dy = s_pos[i*3+1] - s_pos[j*3+1];
        float dz = s_pos[i*3+2] - s_pos[j*3+2];
        float d2 = fmaf(dx,dx, fmaf(dy,dy, dz*dz));
        g_dist[i][j] = (i == j) ? 0.0f : sqrtf(d2);
    }
}

__global__ __launch_bounds__(256, 2)
void loss_kernel(const float* __restrict__ pred,
                 const int*   __restrict__ labels,
                 const float* __restrict__ emb,
                 const float* __restrict__ conn,
                 float* __restrict__ out)
{
    __shared__ __align__(16) float s_act_emb[4][1024];   // 16 KB
    __shared__ float s_pred[64];
    __shared__ int   s_lab[64];
    __shared__ int   s_act[4];
    __shared__ int   s_inact[60];
    __shared__ float s_topk;
    __shared__ float s_dot[4][64];
    __shared__ float s_norm[64];
    __shared__ float s_rn[64];
    __shared__ float s_bce[64], s_pl[64], s_sp[64], s_nw[64];
    __shared__ int   s_islast;
    __shared__ float s_red[256];

    const int b   = blockIdx.x;
    const int tid = threadIdx.x;
    const int w   = tid >> 5, lane = tid & 31;

    // ---------------- Phase A (no sync): smem scalars + per-warp act list ----------------
    if (tid < 64) { s_pred[tid] = pred[b*64 + tid]; s_lab[tid] = labels[b*64 + tid]; }

    const int lab0 = labels[b*64 + lane];
    const int lab1 = labels[b*64 + 32 + lane];
    const unsigned m0 = __ballot_sync(0xffffffffu, lab0 != 0);
    const unsigned m1 = __ballot_sync(0xffffffffu, lab1 != 0);
    int act0, act1, act2, act3;
    {
        int a[4]; int na = 0;
        unsigned mm = m0;
        while (mm) { a[na++] = __ffs(mm) - 1; mm &= mm - 1; }
        mm = m1;
        while (mm) { a[na++] = 32 + __ffs(mm) - 1; mm &= mm - 1; }
        act0 = a[0]; act1 = a[1]; act2 = a[2]; act3 = a[3];
    }

    if (w == 0) {
        const unsigned below = (1u << lane) - 1u;
        if (lab0) s_act[__popc(m0 & below)] = lane;
        if (lab1) s_act[__popc(m0) + __popc(m1 & below)] = 32 + lane;
        const unsigned i0 = ~m0, i1 = ~m1;
        if (!lab0) s_inact[__popc(i0 & below)] = lane;
        if (!lab1) s_inact[__popc(i0) + __popc(i1 & below)] = 32 + lane;
    }

    // ---------------- Phase B (no sync before): stage 4 active rows ----------------
    {
        const float4* base = (const float4*)(emb + (size_t)b * 65536);
        ((float4*)s_act_emb[0])[tid] = base[(size_t)act0 * 256 + tid];
        ((float4*)s_act_emb[1])[tid] = base[(size_t)act1 * 256 + tid];
        ((float4*)s_act_emb[2])[tid] = base[(size_t)act2 * 256 + tid];
        ((float4*)s_act_emb[3])[tid] = base[(size_t)act3 * 256 + tid];
    }

    // warp 0: parallel top-4 + IoU while Phase B loads are in flight
    if (w == 0) {
        float w0 = pred[b*64 + lane];
        float w1 = pred[b*64 + 32 + lane];
        int inter = 0;
        #pragma unroll
        for (int r = 0; r < 4; ++r) {
            float bv; int bi;
            if (w1 > w0) { bv = w1; bi = lane + 32; } else { bv = w0; bi = lane; }
            #pragma unroll
            for (int off = 16; off; off >>= 1) {
                float ov = __shfl_xor_sync(0xffffffffu, bv, off);
                int   oi = __shfl_xor_sync(0xffffffffu, bi, off);
                if (ov > bv || (ov == bv && oi < bi)) { bv = ov; bi = oi; }
            }
            inter += (bi < 32) ? (int)((m0 >> bi) & 1u) : (int)((m1 >> (bi - 32)) & 1u);
            if (bi == lane)      w0 = -1e30f;
            if (bi == lane + 32) w1 = -1e30f;
        }
        if (lane == 0) {
            float un = (float)(8 - inter);
            s_topk = 1.0f - (float)inter / (un + 1e-8f);
        }
    }
    __syncthreads();

    // ---------------- Phase C: 2 rows/pass, 4 passes, f32x2 FMA (R3 form) ----------------
    {
        const ull zero = 0ull;
        #pragma unroll
        for (int pass = 0; pass < 4; ++pass) {
            const int j0 = w * 8 + pass * 2;
            const ulonglong2* r0 = (const ulonglong2*)(emb + (size_t)b * 65536 + (size_t)j0 * 1024);
            const ulonglong2* r1 = r0 + 256;
            ull d00=zero,d01=zero,d02=zero,d03=zero,n0=zero;
            ull d10=zero,d11=zero,d12=zero,d13=zero,n1=zero;
            #pragma unroll
            for (int ii = 0; ii < 8; ++ii) {
                const int i = lane + ii * 32;
                ulonglong2 e0 = r0[i], e1 = r1[i];
                ulonglong2 a0 = ((const ulonglong2*)s_act_emb[0])[i];
                FMA2(d00,e0.x,a0.x,d00); FMA2(d00,e0.y,a0.y,d00);
                FMA2(d10,e1.x,a0.x,d10); FMA2(d10,e1.y,a0.y,d10);
                ulonglong2 a1 = ((const ulonglong2*)s_act_emb[1])[i];
                FMA2(d01,e0.x,a1.x,d01); FMA2(d01,e0.y,a1.y,d01);
                FMA2(d11,e1.x,a1.x,d11); FMA2(d11,e1.y,a1.y,d11);
                ulonglong2 a2 = ((const ulonglong2*)s_act_emb[2])[i];
                FMA2(d02,e0.x,a2.x,d02); FMA2(d02,e0.y,a2.y,d02);
                FMA2(d12,e1.x,a2.x,d12); FMA2(d12,e1.y,a2.y,d12);
                ulonglong2 a3 = ((const ulonglong2*)s_act_emb[3])[i];
                FMA2(d03,e0.x,a3.x,d03); FMA2(d03,e0.y,a3.y,d03);
                FMA2(d13,e1.x,a3.x,d13); FMA2(d13,e1.y,a3.y,d13);
                FMA2(n0 ,e0.x,e0.x,n0 ); FMA2(n0 ,e0.y,e0.y,n0 );
                FMA2(n1 ,e1.x,e1.x,n1 ); FMA2(n1 ,e1.y,e1.y,n1 );
            }
            float v0,v1,v2,v3,v4,v5,v6,v7,v8,v9;
            { float lo,hi; UNPACK2(lo,hi,d00); v0=lo+hi; }
            { float lo,hi; UNPACK2(lo,hi,d01); v1=lo+hi; }
            { float lo,hi; UNPACK2(lo,hi,d02); v2=lo+hi; }
            { float lo,hi; UNPACK2(lo,hi,d03); v3=lo+hi; }
            { float lo,hi; UNPACK2(lo,hi,n0 ); v4=lo+hi; }
            { float lo,hi; UNPACK2(lo,hi,d10); v5=lo+hi; }
            { float lo,hi; UNPACK2(lo,hi,d11); v6=lo+hi; }
            { float lo,hi; UNPACK2(lo,hi,d12); v7=lo+hi; }
            { float lo,hi; UNPACK2(lo,hi,d13); v8=lo+hi; }
            { float lo,hi; UNPACK2(lo,hi,n1 ); v9=lo+hi; }
            #pragma unroll
            for (int off = 16; off; off >>= 1) {
                v0 += __shfl_down_sync(0xffffffffu, v0, off);
                v1 += __shfl_down_sync(0xffffffffu, v1, off);
                v2 += __shfl_down_sync(0xffffffffu, v2, off);
                v3 += __shfl_down_sync(0xffffffffu, v3, off);
                v4 += __shfl_down_sync(0xffffffffu, v4, off);
                v5 += __shfl_down_sync(0xffffffffu, v5, off);
                v6 += __shfl_down_sync(0xffffffffu, v6, off);
                v7 += __shfl_down_sync(0xffffffffu, v7, off);
                v8 += __shfl_down_sync(0xffffffffu, v8, off);
                v9 += __shfl_down_sync(0xffffffffu, v9, off);
            }
            if (lane == 0) {
                s_dot[0][j0]   = v0; s_dot[1][j0]   = v1;
                s_dot[2][j0]   = v2; s_dot[3][j0]   = v3; s_norm[j0]   = v4;
                s_dot[0][j0+1] = v5; s_dot[1][j0+1] = v6;
                s_dot[2][j0+1] = v7; s_dot[3][j0+1] = v8; s_norm[j0+1] = v9;
            }
        }
    }
    __syncthreads();

    // ---------------- Phase D (all warp-parallel now) ----------------
    if (tid < 64) {
        s_rn[tid] = 1.0f / fmaxf(sqrtf(s_norm[tid]), 1e-12f);
        const float p   = s_pred[tid];
        const int   lab = s_lab[tid];
        s_bce[tid] = lab ? logf(p) : log1pf(-p);
        s_pl[tid]  = lab ? p : 0.0f;
    }

    // network + spatial: each warp does 8 rows of conn and Dist (L2-resident)
    {
        const float pl0 = s_pred[lane],        pl1 = s_pred[lane + 32];
        const float ml0 = (pl0 > 0.5f) ? 1.0f : 0.0f;
        const float ml1 = (pl1 > 0.5f) ? 1.0f : 0.0f;
        #pragma unroll
        for (int rr = 0; rr < 8; ++rr) {
            const int r = w * 8 + rr;
            float t1 = fmaf(conn[r*64 + lane],   pl0, conn[r*64 + 32 + lane]   * pl1);
            float t2 = fmaf(g_dist[r][lane],     ml0, g_dist[r][lane + 32]     * ml1);
            #pragma unroll
            for (int off = 16; off; off >>= 1) {
                t1 += __shfl_down_sync(0xffffffffu, t1, off);
                t2 += __shfl_down_sync(0xffffffffu, t2, off);
            }
            if (lane == 0) {
                s_nw[r] = t1 * s_pred[r];
                s_sp[r] = t2 * ((s_pred[r] > 0.5f) ? 1.0f : 0.0f);
            }
        }
    }
    __syncthreads();

    // contrastive: 12 pairs in warp 0
    float ce = 0.0f;
    if (tid < 12) {
        const int p  = tid;
        const int k  = p / 3;
        const int jo = p % 3;
        const int col = jo + (jo >= k ? 1 : 0);
        const int ck = s_act[k];
        const int cj = s_act[col];
        const float rk = s_rn[ck];
        const float l0 = s_dot[k][cj] * rk * s_rn[cj] * INV_TEMP;
        const int base = 20 * jo;
        float mx = l0;
        #pragma unroll
        for (int n = 0; n < 20; ++n) {
            int c = s_inact[base + n];
            float vv = s_dot[k][c] * rk * s_rn[c] * INV_TEMP;
            mx = fmaxf(mx, vv);
        }
        float ssum = expf(l0 - mx);
        #pragma unroll
        for (int n = 0; n < 20; ++n) {
            int c = s_inact[base + n];
            float vv = s_dot[k][c] * rk * s_rn[c] * INV_TEMP;
            ssum += expf(vv - mx);
        }
        ce = logf(ssum) + mx - l0;
    }
    if (tid < 32) {
        #pragma unroll
        for (int off = 16; off; off >>= 1) ce += __shfl_down_sync(0xffffffffu, ce, off);
    }

    if (tid < 32) {
        float r_bce = s_bce[tid] + s_bce[tid+32];
        float r_pl  = s_pl [tid] + s_pl [tid+32];
        float r_p   = s_pred[tid] + s_pred[tid+32];
        float r_lab = (float)s_lab[tid] + (float)s_lab[tid+32];
        float r_sp  = s_sp[tid] + s_sp[tid+32];
        float r_nw  = s_nw[tid] + s_nw[tid+32];
        float pm0 = (s_pred[tid] > 0.5f) ? 1.0f : 0.0f;
        float pm1 = (s_pred[tid+32] > 0.5f) ? 1.0f : 0.0f;
        float r_m = pm0 + pm1;
        #pragma unroll
        for (int off = 16; off; off >>= 1) {
            r_bce += __shfl_down_sync(0xffffffffu, r_bce, off);
            r_pl  += __shfl_down_sync(0xffffffffu, r_pl , off);
            r_p   += __shfl_down_sync(0xffffffffu, r_p  , off);
            r_lab += __shfl_down_sync(0xffffffffu, r_lab, off);
            r_sp  += __shfl_down_sync(0xffffffffu, r_sp , off);
            r_nw  += __shfl_down_sync(0xffffffffu, r_nw , off);
            r_m   += __shfl_down_sync(0xffffffffu, r_m  , off);
        }
        if (tid == 0) {
            float score_b    = -r_bce * (1.0f/64.0f);
            float act_mean   = r_pl / r_lab;
            float inact_mean = (r_p - r_pl) / (64.0f - r_lab);
            float margin_b   = fmaxf(MARGIN_C - (act_mean - inact_mean), 0.0f);
            float contr_b    = ce * (1.0f/12.0f);
            float nm         = r_m;
            float spatial_b  = (nm >= 2.0f) ? r_sp / fmaxf(nm*(nm-1.0f), 1.0f) : 0.0f;
            float net_b      = -r_nw * (1.0f/4096.0f);
            g_partial[b] = 3.0f*score_b + 1.0f*margin_b + 2.0f*s_topk
                         + 1.0f*contr_b + 0.5f*spatial_b + 0.5f*net_b;
        }
    }

    // ---------------- fused final reduction (last block) ----------------
    if (tid == 0) {
        __threadfence();
        unsigned int v = atomicAdd(&g_count, 1u);
        s_islast = (v == (unsigned)(B_SZ - 1));
    }
    __syncthreads();
    if (s_islast) {
        float s = 0.0f;
        for (int i = tid; i < B_SZ; i += blockDim.x) s += g_partial[i];
        s_red[tid] = s;
        __syncthreads();
        for (int o = 128; o > 0; o >>= 1) {
            if (tid < o) s_red[tid] += s_red[tid + o];
            __syncthreads();
        }
        if (tid == 0) { out[0] = s_red[0] * (1.0f / (float)B_SZ); g_count = 0; }
    }
}

extern "C" void kernel_launch(void* const* d_in, const int* in_sizes, int n_in,
                              void* d_out, int out_size)
{
    const float* pred = (const float*)d_in[0];
    const int*   lab  = (const int*)  d_in[1];
    const float* emb  = (const float*)d_in[2];
    const float* cpos = (const float*)d_in[3];
    const float* conn = (const float*)d_in[4];
    dist_kernel<<<1, 256>>>(cpos);
    loss_kernel<<<B_SZ, 256>>>(pred, lab, emb, conn, (float*)d_out);
}